// round 7
// baseline (speedup 1.0000x reference)
#include <cuda_runtime.h>
#include <math.h>

#define HH 1024
#define WW 1024
#define NPIX (HH * WW)
#define NWORDS (WW / 32)          // 32 packed words per row
#define RPB 8                     // rows per block in kernel A

// kernel B tiling
#define CTILE 32                  // columns per block (one mask word)
#define RTILE 256                 // rows per block
#define HALO  32                  // in-shared scan band beyond the tile
#define SROWS (RTILE + 2 * HALO)  // 320 shared rows
#define NB_C (WW / CTILE)         // 32
#define NB_R (HH / RTILE)         // 4
#define TOT_B_BLOCKS (NB_C * NB_R * 2)   // 256

// Scratch (no allocations allowed anywhere)
__device__ unsigned int   g_edgebits[2][HH * NWORDS];  // 256 KB
__device__ unsigned short g_gu[2][NPIX];               // 4 MB: row distances (int), 0xFFFF = row empty
__device__ float          g_blockSums[TOT_B_BLOCKS];

__device__ __forceinline__ unsigned horiz3(unsigned wv, unsigned wl, unsigned wr) {
    return wv & ((wv << 1) | (wl >> 31)) & ((wv >> 1) | (wr << 31));
}

// exact reference g2 for a pixel: normal = (int distance)^2 (fp32-exact);
// sentinel = the reference's empty-row default, same fp32 expression/rounding.
__device__ __forceinline__ float g2_from_u16(unsigned short gu, int col) {
    if (gu == 0xFFFFu) {
        const float jf = (float)col;
        const float gf = fminf(fminf(jf + 1e6f, 1e6f - jf), 1e6f);
        return gf * gf;
    }
    const float gf = (float)gu;
    return gf * gf;
}

// ---------------------------------------------------------------------------
// Kernel A: bit-packed edges + per-row 1D distance, RPB rows per block.
// Per-pixel nearest edge via branch-free 64-bit windows (warp-uniform words);
// exhaustive fallback only when no edge within ~32 cols (prob ~2^-32).
// ---------------------------------------------------------------------------
__global__ void __launch_bounds__(WW) edges_rowdist_kernel(
    const float* __restrict__ preds, const float* __restrict__ targets)
{
    const int r0 = blockIdx.x * RPB;
    const int m  = blockIdx.y;
    const int j  = threadIdx.x;
    const float* __restrict__ seg = (m == 0) ? preds : targets;

    __shared__ unsigned shB[RPB + 2][NWORDS];
    __shared__ unsigned shE[RPB][NWORDS];

    const int t = j >> 5, k = j & 31;

    // load RPB+2 rows (batched for MLP), ballot-pack to bits
    float v[RPB + 2];
    #pragma unroll
    for (int rr = 0; rr < RPB + 2; rr++) {
        const int row = r0 + rr - 1;
        v[rr] = (row >= 0 && row < HH) ? seg[row * WW + j] : 0.0f;
    }
    #pragma unroll
    for (int rr = 0; rr < RPB + 2; rr++) {
        const unsigned b = __ballot_sync(0xffffffffu, v[rr] == 1.0f);
        if (k == 0) shB[rr][t] = b;
    }
    __syncthreads();

    // RPB*NWORDS = 256 threads compute one edge word each
    if (j < RPB * NWORDS) {
        const int w  = j & (NWORDS - 1);
        const int rr = j >> 5;            // NWORDS == 32
        const unsigned hp = horiz3(shB[rr][w],
                                   w > 0 ? shB[rr][w - 1] : 0u,
                                   w < NWORDS - 1 ? shB[rr][w + 1] : 0u);
        const unsigned hc = horiz3(shB[rr + 1][w],
                                   w > 0 ? shB[rr + 1][w - 1] : 0u,
                                   w < NWORDS - 1 ? shB[rr + 1][w + 1] : 0u);
        const unsigned hn = horiz3(shB[rr + 2][w],
                                   w > 0 ? shB[rr + 2][w - 1] : 0u,
                                   w < NWORDS - 1 ? shB[rr + 2][w + 1] : 0u);
        const unsigned e = shB[rr + 1][w] & ~(hp & hc & hn);
        shE[rr][w] = e;
        g_edgebits[m][(r0 + rr) * NWORDS + w] = e;
    }
    __syncthreads();

    // per-pixel nearest edge bit in each of the RPB rows
    #pragma unroll
    for (int rr = 0; rr < RPB; rr++) {
        // warp-uniform word reads (t is the same for all 32 lanes of a warp)
        const unsigned wc = shE[rr][t];
        const unsigned wl = (t > 0)          ? shE[rr][t - 1] : 0u;
        const unsigned wr = (t < NWORDS - 1) ? shE[rr][t + 1] : 0u;

        const unsigned long long L = ((unsigned long long)wc << 32) | wl; // pixel at bit 32+k
        const unsigned long long R = ((unsigned long long)wr << 32) | wc; // pixel at bit k

        const unsigned long long lm = L & (~0ULL >> (31 - k));  // bits <= pixel
        const unsigned long long rm = R & (~0ULL << k);         // bits >= pixel

        float dl, dr;
        if (lm) {
            dl = (float)(__clzll((long long)lm) - (31 - k));    // 0 if pixel is edge
        } else {
            // cold path: no edge in cols [j-(32+k) .. j]
            int tt = t - 2;
            while (tt >= 0 && shE[rr][tt] == 0u) tt--;
            if (tt >= 0) dl = (float)(j - (tt * 32 + (31 - __clz(shE[rr][tt]))));
            else         dl = (float)j + 1e6f;                  // reference default
        }
        if (rm) {
            dr = (float)(__ffsll((long long)rm) - 1 - k);       // 0 if pixel is edge
        } else {
            int tt = t + 2;
            while (tt < NWORDS && shE[rr][tt] == 0u) tt++;
            if (tt < NWORDS) dr = (float)((tt * 32 + (__ffs(shE[rr][tt]) - 1)) - j);
            else             dr = 1e6f - (float)j;              // reference default
        }

        const float g = fminf(fminf(dl, dr), 1e6f);
        // g <= 1023 iff the row contains any edge; otherwise sentinel
        g_gu[m][(r0 + rr) * WW + j] =
            (g < 1024.0f) ? (unsigned short)g : (unsigned short)0xFFFFu;
    }
}

// ---------------------------------------------------------------------------
// Kernel B: column lower-envelope in shared-memory tiles (32 cols x 256 rows
// + 32-row halo). uint16 distances are converted to exact fp32 g^2 during
// staging (sentinel -> reference's empty-row default, identical rounding).
// Scan loop: LDS hits, exact d^2 >= best prune; beyond-halo pixels fall back
// to global (essentially never taken). Deterministic reduction, no fences.
// ---------------------------------------------------------------------------
__global__ void __launch_bounds__(1024) colpass_kernel()
{
    const int c0 = blockIdx.x * CTILE;
    const int t0 = blockIdx.y * RTILE;
    const int m  = blockIdx.z;

    __shared__ float    sh[SROWS][CTILE];
    __shared__ unsigned shM[RTILE];

    const int tid = threadIdx.x;
    const int c   = tid & 31;        // column within tile
    const int rg  = tid >> 5;        // 0..31
    const int col = c0 + c;
    const unsigned short* __restrict__ gu = g_gu[m];

    // stage tile + halo, converting to exact fp32 g^2
    #pragma unroll
    for (int rr = rg; rr < SROWS; rr += 32) {
        const int row = t0 - HALO + rr;
        sh[rr][c] = (row >= 0 && row < HH)
                  ? g2_from_u16(gu[row * WW + col], col)
                  : 3e37f;
    }
    if (tid < RTILE)
        shM[tid] = g_edgebits[1 - m][(t0 + tid) * NWORDS + (c0 >> 5)];
    __syncthreads();

    float acc = 0.0f;
    #pragma unroll
    for (int q = 0; q < RTILE / 32; q++) {
        const int rl = rg + 32 * q;          // row within tile
        if ((shM[rl] >> c) & 1u) {
            const int r  = t0 + rl;          // global row
            const int sr = rl + HALO;        // shared row index
            float best = sh[sr][c];
            int d = 1;
            while ((float)(d * d) < best) {  // exact prune
                const float vu = (sr - d >= 0)
                    ? sh[sr - d][c]
                    : ((r - d >= 0) ? g2_from_u16(gu[(r - d) * WW + col], col) : 3e37f);
                const float vd = (sr + d < SROWS)
                    ? sh[sr + d][c]
                    : ((r + d < HH) ? g2_from_u16(gu[(r + d) * WW + col], col) : 3e37f);
                best = fminf(best, fminf(vu, vd) + (float)(d * d));
                d++;
                if (r - d < 0 && r + d >= HH) break;
            }
            acc += sqrtf(best);
        }
    }

    // deterministic in-block reduction
    float s = acc;
    #pragma unroll
    for (int o = 16; o > 0; o >>= 1) s += __shfl_down_sync(0xffffffffu, s, o);

    __shared__ float warpsum[32];
    if (c == 0) warpsum[rg] = s;
    __syncthreads();

    if (tid < 32) {
        float w = warpsum[tid];
        #pragma unroll
        for (int o = 16; o > 0; o >>= 1) w += __shfl_down_sync(0xffffffffu, w, o);
        if (tid == 0)
            g_blockSums[(m * NB_R + blockIdx.y) * NB_C + blockIdx.x] = w;
    }
}

// ---------------------------------------------------------------------------
// Kernel C: deterministic final reduction + sigmoid.
// ---------------------------------------------------------------------------
__global__ void __launch_bounds__(256) finalize_kernel(float* __restrict__ out)
{
    __shared__ float sh[256];
    sh[threadIdx.x] = g_blockSums[threadIdx.x];   // TOT_B_BLOCKS == 256
    __syncthreads();
    #pragma unroll
    for (int stride = 128; stride > 0; stride >>= 1) {
        if (threadIdx.x < stride) sh[threadIdx.x] += sh[threadIdx.x + stride];
        __syncthreads();
    }
    if (threadIdx.x == 0) {
        const float loss = sh[0] / (2.0f * (float)NPIX);
        out[0] = 1.0f / (1.0f + expf(-loss));
    }
}

// ---------------------------------------------------------------------------
extern "C" void kernel_launch(void* const* d_in, const int* in_sizes, int n_in,
                              void* d_out, int out_size)
{
    const float* preds   = (const float*)d_in[0];
    const float* targets = (const float*)d_in[1];
    float* out = (float*)d_out;
    (void)in_sizes; (void)n_in; (void)out_size;

    dim3 gridA(HH / RPB, 2);
    edges_rowdist_kernel<<<gridA, WW>>>(preds, targets);

    dim3 gridB(NB_C, NB_R, 2);
    colpass_kernel<<<gridB, 1024>>>();

    finalize_kernel<<<1, 256>>>(out);
}

// round 8
// speedup vs baseline: 1.1487x; 1.1487x over previous
#include <cuda_runtime.h>
#include <math.h>

#define HH 1024
#define WW 1024
#define NPIX (HH * WW)
#define NWORDS (WW / 32)          // 32 packed words per row
#define RPB 8                     // rows per block in kernel A

// kernel B tiling
#define CTILE 32                  // columns per block (one mask word)
#define RTILE 256                 // rows per block
#define HALO  32                  // in-shared scan band beyond the tile
#define SROWS (RTILE + 2 * HALO)  // 320 shared rows
#define NB_C (WW / CTILE)         // 32
#define NB_R (HH / RTILE)         // 4
#define TOT_B_BLOCKS (NB_C * NB_R * 2)   // 256

// Scratch (no allocations allowed anywhere)
__device__ unsigned int g_edgebits[2][HH * NWORDS];   // 256 KB
__device__ float        g_g2[2][NPIX];                // 8 MB
__device__ float        g_blockSums[TOT_B_BLOCKS];

__device__ __forceinline__ unsigned horiz3(unsigned wv, unsigned wl, unsigned wr) {
    return wv & ((wv << 1) | (wl >> 31)) & ((wv >> 1) | (wr << 31));
}

// ---------------------------------------------------------------------------
// Kernel A: bit-packed edges + per-row 1D distance, RPB rows per block.
// Per-pixel nearest edge via a 64-bit window around the pixel:
//   - edge pixels fall out automatically (own bit in window -> d=0)
//   - hot path is branch-free; ONE rare fallback region (border columns /
//     sparse rows only), containing the reference's exact 1e6 defaults.
// ---------------------------------------------------------------------------
__global__ void __launch_bounds__(WW) edges_rowdist_kernel(
    const float* __restrict__ preds, const float* __restrict__ targets)
{
    const int r0 = blockIdx.x * RPB;
    const int m  = blockIdx.y;
    const int j  = threadIdx.x;
    const float* __restrict__ seg = (m == 0) ? preds : targets;

    __shared__ unsigned shB[RPB + 2][NWORDS];
    __shared__ unsigned shE[RPB][NWORDS];

    const int t = j >> 5, k = j & 31;

    // load RPB+2 rows (batched for MLP), ballot-pack to bits
    float v[RPB + 2];
    #pragma unroll
    for (int rr = 0; rr < RPB + 2; rr++) {
        const int row = r0 + rr - 1;
        v[rr] = (row >= 0 && row < HH) ? seg[row * WW + j] : 0.0f;
    }
    #pragma unroll
    for (int rr = 0; rr < RPB + 2; rr++) {
        const unsigned b = __ballot_sync(0xffffffffu, v[rr] == 1.0f);
        if (k == 0) shB[rr][t] = b;
    }
    __syncthreads();

    // RPB*NWORDS = 256 threads compute one edge word each
    if (j < RPB * NWORDS) {
        const int w  = j & (NWORDS - 1);
        const int rr = j >> 5;            // NWORDS == 32
        const unsigned hp = horiz3(shB[rr][w],
                                   w > 0 ? shB[rr][w - 1] : 0u,
                                   w < NWORDS - 1 ? shB[rr][w + 1] : 0u);
        const unsigned hc = horiz3(shB[rr + 1][w],
                                   w > 0 ? shB[rr + 1][w - 1] : 0u,
                                   w < NWORDS - 1 ? shB[rr + 1][w + 1] : 0u);
        const unsigned hn = horiz3(shB[rr + 2][w],
                                   w > 0 ? shB[rr + 2][w - 1] : 0u,
                                   w < NWORDS - 1 ? shB[rr + 2][w + 1] : 0u);
        const unsigned e = shB[rr + 1][w] & ~(hp & hc & hn);
        shE[rr][w] = e;
        g_edgebits[m][(r0 + rr) * NWORDS + w] = e;
    }
    __syncthreads();

    // per-pixel nearest edge bit in each of the RPB rows
    #pragma unroll
    for (int rr = 0; rr < RPB; rr++) {
        const unsigned wc = shE[rr][t];
        const unsigned wl = (t > 0)          ? shE[rr][t - 1] : 0u;
        const unsigned wr = (t < NWORDS - 1) ? shE[rr][t + 1] : 0u;

        const unsigned long long L = ((unsigned long long)wc << 32) | wl; // pixel at bit 32+k
        const unsigned long long R = ((unsigned long long)wr << 32) | wc; // pixel at bit k
        const unsigned long long lm = L & (~0ULL >> (31 - k));  // bits <= pixel pos
        const unsigned long long rm = R & (~0ULL << k);         // bits >= pixel pos

        float g;
        if (lm != 0ULL && rm != 0ULL) {
            // hot path: branch-free; edge pixels give dl = dr = 0
            const int dl = __clzll((long long)lm) - (31 - k);
            const int dr = __ffsll((long long)rm) - 1 - k;
            g = (float)min(dl, dr);          // <= ~64, far below the 1e6 cap
        } else {
            // rare: border columns or nearly-empty rows — full exact logic
            float dl, dr;
            if (lm) {
                dl = (float)(__clzll((long long)lm) - (31 - k));
            } else {
                int tt = t - 2;
                while (tt >= 0 && shE[rr][tt] == 0u) tt--;
                if (tt >= 0) dl = (float)(j - (tt * 32 + (31 - __clz(shE[rr][tt]))));
                else         dl = (float)j + 1e6f;      // reference default, exact fp32
            }
            if (rm) {
                dr = (float)(__ffsll((long long)rm) - 1 - k);
            } else {
                int tt = t + 2;
                while (tt < NWORDS && shE[rr][tt] == 0u) tt++;
                if (tt < NWORDS) dr = (float)((tt * 32 + (__ffs(shE[rr][tt]) - 1)) - j);
                else             dr = 1e6f - (float)j;  // reference default, exact fp32
            }
            g = fminf(fminf(dl, dr), 1e6f);
        }
        g_g2[m][(r0 + rr) * WW + j] = g * g;
    }
}

// ---------------------------------------------------------------------------
// Kernel B: column lower-envelope in shared-memory tiles (32 cols x 256 rows
// + 32-row halo staged to LDS). Exact candidates, exact d^2 >= best prune;
// beyond-halo pixels fall back to global (essentially never). Masked pixels
// with g2 == 0 contribute sqrt(0) = 0 and are skipped exactly.
// Deterministic in-block reduction; no fences, no atomics.
// ---------------------------------------------------------------------------
__global__ void __launch_bounds__(1024) colpass_kernel()
{
    const int c0 = blockIdx.x * CTILE;
    const int t0 = blockIdx.y * RTILE;
    const int m  = blockIdx.z;

    __shared__ float    sh[SROWS][CTILE];
    __shared__ unsigned shM[RTILE];

    const int tid = threadIdx.x;
    const int c   = tid & 31;        // column within tile
    const int rg  = tid >> 5;        // 0..31
    const float* __restrict__ g2 = g_g2[m];

    // stage g2 tile + halo (coalesced: each warp loads one 128B row stripe)
    #pragma unroll
    for (int rr = rg; rr < SROWS; rr += 32) {
        const int row = t0 - HALO + rr;
        sh[rr][c] = (row >= 0 && row < HH) ? g2[row * WW + c0 + c] : 3e37f;
    }
    if (tid < RTILE)
        shM[tid] = g_edgebits[1 - m][(t0 + tid) * NWORDS + (c0 >> 5)];
    __syncthreads();

    float acc = 0.0f;
    #pragma unroll
    for (int q = 0; q < RTILE / 32; q++) {
        const int rl = rg + 32 * q;          // row within tile
        const int sr = rl + HALO;            // shared row index
        if (((shM[rl] >> c) & 1u) && sh[sr][c] != 0.0f) {
            const int r = t0 + rl;           // global row
            float best = sh[sr][c];
            int d = 1;
            while ((float)(d * d) < best) {  // exact prune
                const float vu = (sr - d >= 0)
                    ? sh[sr - d][c]
                    : ((r - d >= 0) ? g2[(r - d) * WW + c0 + c] : 3e37f);
                const float vd = (sr + d < SROWS)
                    ? sh[sr + d][c]
                    : ((r + d < HH) ? g2[(r + d) * WW + c0 + c] : 3e37f);
                best = fminf(best, fminf(vu, vd) + (float)(d * d));
                d++;
                if (r - d < 0 && r + d >= HH) break;
            }
            acc += sqrtf(best);
        }
    }

    // deterministic in-block reduction
    float s = acc;
    #pragma unroll
    for (int o = 16; o > 0; o >>= 1) s += __shfl_down_sync(0xffffffffu, s, o);

    __shared__ float warpsum[32];
    if (c == 0) warpsum[rg] = s;
    __syncthreads();

    if (tid < 32) {
        float w = warpsum[tid];
        #pragma unroll
        for (int o = 16; o > 0; o >>= 1) w += __shfl_down_sync(0xffffffffu, w, o);
        if (tid == 0)
            g_blockSums[(m * NB_R + blockIdx.y) * NB_C + blockIdx.x] = w;
    }
}

// ---------------------------------------------------------------------------
// Kernel C: deterministic final reduction + sigmoid.
// ---------------------------------------------------------------------------
__global__ void __launch_bounds__(256) finalize_kernel(float* __restrict__ out)
{
    __shared__ float sh[256];
    sh[threadIdx.x] = g_blockSums[threadIdx.x];   // TOT_B_BLOCKS == 256
    __syncthreads();
    #pragma unroll
    for (int stride = 128; stride > 0; stride >>= 1) {
        if (threadIdx.x < stride) sh[threadIdx.x] += sh[threadIdx.x + stride];
        __syncthreads();
    }
    if (threadIdx.x == 0) {
        const float loss = sh[0] / (2.0f * (float)NPIX);
        out[0] = 1.0f / (1.0f + expf(-loss));
    }
}

// ---------------------------------------------------------------------------
extern "C" void kernel_launch(void* const* d_in, const int* in_sizes, int n_in,
                              void* d_out, int out_size)
{
    const float* preds   = (const float*)d_in[0];
    const float* targets = (const float*)d_in[1];
    float* out = (float*)d_out;
    (void)in_sizes; (void)n_in; (void)out_size;

    dim3 gridA(HH / RPB, 2);
    edges_rowdist_kernel<<<gridA, WW>>>(preds, targets);

    dim3 gridB(NB_C, NB_R, 2);
    colpass_kernel<<<gridB, 1024>>>();

    finalize_kernel<<<1, 256>>>(out);
}